// round 2
// baseline (speedup 1.0000x reference)
#include <cuda_runtime.h>
#include <math.h>

// Problem constants (fixed by the registry shapes): B=4, H=8, N=128, L=128, D=64.
#define LSEQ 128
#define DH   64
#define NTHREADS 128
#define CHUNK 8

// One CTA per (b,h,n) attention problem. 128 threads; thread r owns query row r.
// K and V for the problem are staged in shared memory (64 KB); all threads read
// the same K/V row in lockstep -> pure smem broadcast, conflict-free.
// Online softmax (flash-style) so no S matrix is materialized.
// __launch_bounds__(128,2): 2 CTAs/SM (128 KB smem, <=256 regs/thread) for
// latency hiding of MUFU/LDS chains.
__global__ __launch_bounds__(NTHREADS, 2)
void attn_fwd_kernel(const float* __restrict__ q,
                     const float* __restrict__ k,
                     const float* __restrict__ v,
                     const int*   __restrict__ mask,
                     float*       __restrict__ out,
                     int HN)   // H*N, for recovering batch index b
{
    extern __shared__ float smem[];
    float* Ks = smem;                 // [LSEQ][DH]
    float* Vs = smem + LSEQ * DH;     // [LSEQ][DH]

    const int p   = blockIdx.x;       // flattened (b*H + h)*N + n
    const int tid = threadIdx.x;      // query row
    const size_t base = (size_t)p * (LSEQ * DH);

    const int b = p / HN;
    const int n = p % LSEQ;           // N == 128 == LSEQ for this problem
    const int* mrow = mask + ((size_t)(b * LSEQ + n)) * (LSEQ * LSEQ)
                           + (size_t)tid * LSEQ;

    // ---- cooperative load of K and V tiles (coalesced float4) ----
    {
        const float4* kg = (const float4*)(k + base);
        const float4* vg = (const float4*)(v + base);
        float4* ks4 = (float4*)Ks;
        float4* vs4 = (float4*)Vs;
        #pragma unroll
        for (int i = 0; i < (LSEQ * DH / 4) / NTHREADS; i++) {
            ks4[tid + i * NTHREADS] = kg[tid + i * NTHREADS];
            vs4[tid + i * NTHREADS] = vg[tid + i * NTHREADS];
        }
    }

    // ---- own q row into registers ----
    float4 qr[DH / 4];
    {
        const float4* qg = (const float4*)(q + base + (size_t)tid * DH);
        #pragma unroll
        for (int i = 0; i < DH / 4; i++) qr[i] = qg[i];
    }

    __syncthreads();

    float  mmax = -INFINITY;
    float  lsum = 0.0f;
    float4 o[DH / 4];
    #pragma unroll
    for (int i = 0; i < DH / 4; i++) o[i] = make_float4(0.f, 0.f, 0.f, 0.f);

    #pragma unroll 1
    for (int j0 = 0; j0 < LSEQ; j0 += CHUNK) {
        // mask values for this chunk (vectorized int4 loads)
        int4 mv0 = *(const int4*)(mrow + j0);
        int4 mv1 = *(const int4*)(mrow + j0 + 4);
        int mv[CHUNK] = { mv0.x, mv0.y, mv0.z, mv0.w,
                          mv1.x, mv1.y, mv1.z, mv1.w };

        // ---- scores s[jj] = q . K[j0+jj]  (8-way ILP accumulators) ----
        float s[CHUNK];
        #pragma unroll
        for (int jj = 0; jj < CHUNK; jj++) s[jj] = 0.0f;

        #pragma unroll
        for (int d4 = 0; d4 < DH / 4; d4++) {
            const float4 qv = qr[d4];
            #pragma unroll
            for (int jj = 0; jj < CHUNK; jj++) {
                const float4 kv = *(const float4*)&Ks[(j0 + jj) * DH + d4 * 4];
                s[jj] = fmaf(qv.x, kv.x, s[jj]);
                s[jj] = fmaf(qv.y, kv.y, s[jj]);
                s[jj] = fmaf(qv.z, kv.z, s[jj]);
                s[jj] = fmaf(qv.w, kv.w, s[jj]);
            }
        }

        // temperature + mask fill (matches reference: mask applied AFTER /8)
        float cmax = mmax;
        #pragma unroll
        for (int jj = 0; jj < CHUNK; jj++) {
            s[jj] = (mv[jj] == 0) ? -32768.0f : s[jj] * 0.125f;
            cmax  = fmaxf(cmax, s[jj]);
        }

        // online softmax rescale
        const float scale = __expf(mmax - cmax);   // exp(-inf)=0 on first chunk
        mmax = cmax;
        lsum *= scale;
        #pragma unroll
        for (int i = 0; i < DH / 4; i++) {
            o[i].x *= scale; o[i].y *= scale; o[i].z *= scale; o[i].w *= scale;
        }

        float pj[CHUNK];
        #pragma unroll
        for (int jj = 0; jj < CHUNK; jj++) {
            pj[jj] = __expf(s[jj] - mmax);
            lsum  += pj[jj];
        }

        // ---- O += P . V ----
        #pragma unroll
        for (int d4 = 0; d4 < DH / 4; d4++) {
            float4 ov = o[d4];
            #pragma unroll
            for (int jj = 0; jj < CHUNK; jj++) {
                const float4 vv = *(const float4*)&Vs[(j0 + jj) * DH + d4 * 4];
                ov.x = fmaf(pj[jj], vv.x, ov.x);
                ov.y = fmaf(pj[jj], vv.y, ov.y);
                ov.z = fmaf(pj[jj], vv.z, ov.z);
                ov.w = fmaf(pj[jj], vv.w, ov.w);
            }
            o[d4] = ov;
        }
    }

    // ---- normalize and store ----
    const float inv = 1.0f / lsum;
    float4* og = (float4*)(out + base + (size_t)tid * DH);
    #pragma unroll
    for (int i = 0; i < DH / 4; i++) {
        float4 t = o[i];
        t.x *= inv; t.y *= inv; t.z *= inv; t.w *= inv;
        og[i] = t;
    }
}

extern "C" void kernel_launch(void* const* d_in, const int* in_sizes, int n_in,
                              void* d_out, int out_size)
{
    const float* q    = (const float*)d_in[0];
    const float* k    = (const float*)d_in[1];
    const float* v    = (const float*)d_in[2];
    const int*   mask = (const int*)d_in[3];
    float*       out  = (float*)d_out;

    // Derive sizes: q has nprob * L * D elements; mask has (B*N) * L * L.
    const int nprob = in_sizes[0] / (LSEQ * DH);     // B*H*N
    const int nmask = in_sizes[3] / (LSEQ * LSEQ);   // B*N
    const int HN    = (nprob / nmask) * LSEQ;        // H*N  (N == 128)

    const int smem_bytes = 2 * LSEQ * DH * (int)sizeof(float);  // 64 KB
    cudaFuncSetAttribute(attn_fwd_kernel,
                         cudaFuncAttributeMaxDynamicSharedMemorySize,
                         smem_bytes);

    attn_fwd_kernel<<<nprob, NTHREADS, smem_bytes>>>(q, k, v, mask, out, HN);
}

// round 3
// speedup vs baseline: 3.0092x; 3.0092x over previous
#include <cuda_runtime.h>
#include <math.h>

// B=4, H=8, N=128, Lq=Lk=128, D=64. One CTA per (b,h,n); 4 warps; warp owns 32 q rows.
#define LSEQ 128
#define DH   64
#define NTHREADS 128
#define KSTRIDE 76   // floats; 76 mod 32 == 12 -> conflict-free for both mma fragment patterns

__device__ __forceinline__ unsigned int f2tf32(float f) {
    unsigned int u;
    asm("cvt.rna.tf32.f32 %0, %1;" : "=r"(u) : "f"(f));
    return u;
}

__device__ __forceinline__ void mma_tf32(float* d, const unsigned int* a,
                                         unsigned int b0, unsigned int b1) {
    asm volatile(
        "mma.sync.aligned.m16n8k8.row.col.f32.tf32.tf32.f32 "
        "{%0,%1,%2,%3}, {%4,%5,%6,%7}, {%8,%9}, {%0,%1,%2,%3};"
        : "+f"(d[0]), "+f"(d[1]), "+f"(d[2]), "+f"(d[3])
        : "r"(a[0]), "r"(a[1]), "r"(a[2]), "r"(a[3]), "r"(b0), "r"(b1));
}

__global__ __launch_bounds__(NTHREADS, 2)
void attn_mma_kernel(const float* __restrict__ q,
                     const float* __restrict__ k,
                     const float* __restrict__ v,
                     const int*   __restrict__ mask,
                     float*       __restrict__ out,
                     int HN)
{
    extern __shared__ unsigned int smem_u[];
    unsigned int* Ks = smem_u;                       // [128][KSTRIDE] tf32 bits
    unsigned int* Vs = smem_u + LSEQ * KSTRIDE;      // [128][KSTRIDE] tf32 bits
    unsigned char* Mb = (unsigned char*)(Vs + LSEQ * KSTRIDE);  // [128][128] mask bytes

    const int p    = blockIdx.x;
    const int tid  = threadIdx.x;
    const int wid  = tid >> 5;
    const int lane = tid & 31;
    const int g    = lane >> 2;      // group id (row within fragment)
    const int t    = lane & 3;       // thread-in-group (col pair id)
    const size_t base = (size_t)p * (LSEQ * DH);

    const int b = p / HN;
    const int n = p % LSEQ;

    // ---- stage K, V (converted to tf32) into smem, coalesced float4 ----
    {
        const float4* kg = (const float4*)(k + base);
        const float4* vg = (const float4*)(v + base);
        #pragma unroll
        for (int i = tid; i < LSEQ * (DH / 4); i += NTHREADS) {
            const int row = i >> 4, c4 = i & 15;
            float4 kv = kg[i];
            float4 vv = vg[i];
            uint4 ku = { f2tf32(kv.x), f2tf32(kv.y), f2tf32(kv.z), f2tf32(kv.w) };
            uint4 vu = { f2tf32(vv.x), f2tf32(vv.y), f2tf32(vv.z), f2tf32(vv.w) };
            *(uint4*)(Ks + row * KSTRIDE + c4 * 4) = ku;
            *(uint4*)(Vs + row * KSTRIDE + c4 * 4) = vu;
        }
        // mask ints -> bytes
        const int4* mg = (const int4*)(mask + ((size_t)(b * LSEQ + n)) * (LSEQ * LSEQ));
        #pragma unroll
        for (int i = tid; i < (LSEQ * LSEQ) / 4; i += NTHREADS) {
            int4 m4 = mg[i];
            uchar4 u = { (unsigned char)m4.x, (unsigned char)m4.y,
                         (unsigned char)m4.z, (unsigned char)m4.w };
            ((uchar4*)Mb)[i] = u;
        }
    }

    // ---- Q fragments (tf32) in registers: warp rows [32*wid, 32*wid+32) ----
    unsigned int qa[2][8][4];   // [m-tile][k-step][frag]
    {
        const float* qp = q + base;
        #pragma unroll
        for (int mt = 0; mt < 2; mt++) {
            const int r0 = 32 * wid + 16 * mt + g;
            #pragma unroll
            for (int ks = 0; ks < 8; ks++) {
                const int c0 = 8 * ks + t;
                qa[mt][ks][0] = f2tf32(qp[(r0)     * DH + c0]);
                qa[mt][ks][1] = f2tf32(qp[(r0 + 8) * DH + c0]);
                qa[mt][ks][2] = f2tf32(qp[(r0)     * DH + c0 + 4]);
                qa[mt][ks][3] = f2tf32(qp[(r0 + 8) * DH + c0 + 4]);
            }
        }
    }

    __syncthreads();

    // ---- online softmax state & O accumulators ----
    float mrow[2][2], lrow[2][2];
    #pragma unroll
    for (int mt = 0; mt < 2; mt++)
        for (int h = 0; h < 2; h++) { mrow[mt][h] = -INFINITY; lrow[mt][h] = 0.0f; }

    float oacc[2][8][4];
    #pragma unroll
    for (int mt = 0; mt < 2; mt++)
        for (int nt = 0; nt < 8; nt++)
            for (int e = 0; e < 4; e++) oacc[mt][nt][e] = 0.0f;

    const int g4 = lane & ~3;
    const int sl1 = g4 | (t >> 1);
    const int sl2 = g4 | ((t >> 1) + 2);
    const bool odd = t & 1;

    // ================= main loop over 4 key-blocks of 32 =================
    #pragma unroll 1
    for (int kb = 0; kb < 4; kb++) {
        const int key0 = kb * 32;

        // ---- S = Q @ K^T for this block: sfr[mt][nt] is a 16x8 C-frag ----
        float sfr[2][4][4];
        #pragma unroll
        for (int mt = 0; mt < 2; mt++)
            for (int nt = 0; nt < 4; nt++)
                for (int e = 0; e < 4; e++) sfr[mt][nt][e] = 0.0f;

        #pragma unroll
        for (int nt = 0; nt < 4; nt++) {
            const unsigned int* krow = Ks + (key0 + 8 * nt + g) * KSTRIDE;
            #pragma unroll
            for (int ks = 0; ks < 8; ks++) {
                const unsigned int b0 = krow[8 * ks + t];
                const unsigned int b1 = krow[8 * ks + t + 4];
                mma_tf32(sfr[0][nt], qa[0][ks], b0, b1);
                mma_tf32(sfr[1][nt], qa[1][ks], b0, b1);
            }
        }

        // ---- scale + mask + row max ----
        float bm[2][2] = { { -INFINITY, -INFINITY }, { -INFINITY, -INFINITY } };
        #pragma unroll
        for (int mt = 0; mt < 2; mt++) {
            #pragma unroll
            for (int h = 0; h < 2; h++) {
                const int rr = 32 * wid + 16 * mt + g + 8 * h;
                const unsigned char* mrowp = Mb + rr * LSEQ + key0 + 2 * t;
                #pragma unroll
                for (int nt = 0; nt < 4; nt++) {
                    const unsigned char m0 = mrowp[8 * nt];
                    const unsigned char m1 = mrowp[8 * nt + 1];
                    float e0 = sfr[mt][nt][2 * h];
                    float e1 = sfr[mt][nt][2 * h + 1];
                    e0 = m0 ? e0 * 0.125f : -32768.0f;
                    e1 = m1 ? e1 * 0.125f : -32768.0f;
                    sfr[mt][nt][2 * h]     = e0;
                    sfr[mt][nt][2 * h + 1] = e1;
                    bm[mt][h] = fmaxf(bm[mt][h], fmaxf(e0, e1));
                }
            }
        }
        // quad reduce (lanes differing in bits 0-1 share the row)
        #pragma unroll
        for (int mt = 0; mt < 2; mt++)
            #pragma unroll
            for (int h = 0; h < 2; h++) {
                float x = bm[mt][h];
                x = fmaxf(x, __shfl_xor_sync(0xffffffff, x, 1));
                x = fmaxf(x, __shfl_xor_sync(0xffffffff, x, 2));
                bm[mt][h] = x;
            }

        // ---- online update: alpha, p = exp(s - mnew), sums ----
        float alpha[2][2];
        float rs[2][2] = { {0.f, 0.f}, {0.f, 0.f} };
        #pragma unroll
        for (int mt = 0; mt < 2; mt++)
            #pragma unroll
            for (int h = 0; h < 2; h++) {
                const float mnew = fmaxf(mrow[mt][h], bm[mt][h]);
                alpha[mt][h] = __expf(mrow[mt][h] - mnew);  // 0 on first block
                mrow[mt][h] = mnew;
            }

        #pragma unroll
        for (int mt = 0; mt < 2; mt++)
            #pragma unroll
            for (int nt = 0; nt < 4; nt++)
                #pragma unroll
                for (int h = 0; h < 2; h++) {
                    float p0 = __expf(sfr[mt][nt][2 * h]     - mrow[mt][h]);
                    float p1 = __expf(sfr[mt][nt][2 * h + 1] - mrow[mt][h]);
                    sfr[mt][nt][2 * h]     = p0;
                    sfr[mt][nt][2 * h + 1] = p1;
                    rs[mt][h] += p0 + p1;
                }

        #pragma unroll
        for (int mt = 0; mt < 2; mt++)
            #pragma unroll
            for (int h = 0; h < 2; h++) {
                float x = rs[mt][h];
                x += __shfl_xor_sync(0xffffffff, x, 1);
                x += __shfl_xor_sync(0xffffffff, x, 2);
                lrow[mt][h] = lrow[mt][h] * alpha[mt][h] + x;
            }

        // rescale O
        #pragma unroll
        for (int mt = 0; mt < 2; mt++)
            #pragma unroll
            for (int nt = 0; nt < 8; nt++) {
                oacc[mt][nt][0] *= alpha[mt][0];
                oacc[mt][nt][1] *= alpha[mt][0];
                oacc[mt][nt][2] *= alpha[mt][1];
                oacc[mt][nt][3] *= alpha[mt][1];
            }

        // ---- relayout P: C-frag -> A-frag via shuffles, convert tf32 ----
        unsigned int pa[2][4][4];
        #pragma unroll
        for (int mt = 0; mt < 2; mt++)
            #pragma unroll
            for (int ks = 0; ks < 4; ks++) {
                const float c0 = sfr[mt][ks][0], c1 = sfr[mt][ks][1];
                const float c2 = sfr[mt][ks][2], c3 = sfr[mt][ks][3];
                float u0 = __shfl_sync(0xffffffff, c0, sl1);
                float u1 = __shfl_sync(0xffffffff, c1, sl1);
                float u2 = __shfl_sync(0xffffffff, c2, sl1);
                float u3 = __shfl_sync(0xffffffff, c3, sl1);
                float w0 = __shfl_sync(0xffffffff, c0, sl2);
                float w1 = __shfl_sync(0xffffffff, c1, sl2);
                float w2 = __shfl_sync(0xffffffff, c2, sl2);
                float w3 = __shfl_sync(0xffffffff, c3, sl2);
                pa[mt][ks][0] = f2tf32(odd ? u1 : u0);
                pa[mt][ks][1] = f2tf32(odd ? u3 : u2);
                pa[mt][ks][2] = f2tf32(odd ? w1 : w0);
                pa[mt][ks][3] = f2tf32(odd ? w3 : w2);
            }

        // ---- O += P @ V ----
        #pragma unroll
        for (int ks = 0; ks < 4; ks++) {
            const unsigned int* vrow0 = Vs + (key0 + 8 * ks + t) * KSTRIDE;
            const unsigned int* vrow1 = Vs + (key0 + 8 * ks + t + 4) * KSTRIDE;
            #pragma unroll
            for (int nt = 0; nt < 8; nt++) {
                const unsigned int b0 = vrow0[8 * nt + g];
                const unsigned int b1 = vrow1[8 * nt + g];
                mma_tf32(oacc[0][nt], pa[0][ks], b0, b1);
                mma_tf32(oacc[1][nt], pa[1][ks], b0, b1);
            }
        }
    }

    // ---- epilogue: normalize and store (float2 per pair of cols) ----
    #pragma unroll
    for (int mt = 0; mt < 2; mt++) {
        const float inv0 = 1.0f / lrow[mt][0];
        const float inv1 = 1.0f / lrow[mt][1];
        const int r0 = 32 * wid + 16 * mt + g;
        #pragma unroll
        for (int nt = 0; nt < 8; nt++) {
            const int col = 8 * nt + 2 * t;
            float2 lo = { oacc[mt][nt][0] * inv0, oacc[mt][nt][1] * inv0 };
            float2 hi = { oacc[mt][nt][2] * inv1, oacc[mt][nt][3] * inv1 };
            *(float2*)(out + base + (size_t)(r0)     * DH + col) = lo;
            *(float2*)(out + base + (size_t)(r0 + 8) * DH + col) = hi;
        }
    }
}

extern "C" void kernel_launch(void* const* d_in, const int* in_sizes, int n_in,
                              void* d_out, int out_size)
{
    const float* q    = (const float*)d_in[0];
    const float* k    = (const float*)d_in[1];
    const float* v    = (const float*)d_in[2];
    const int*   mask = (const int*)d_in[3];
    float*       out  = (float*)d_out;

    const int nprob = in_sizes[0] / (LSEQ * DH);     // B*H*N
    const int nmask = in_sizes[3] / (LSEQ * LSEQ);   // B*N
    const int HN    = (nprob / nmask) * LSEQ;        // H*N

    const int smem_bytes = 2 * LSEQ * KSTRIDE * (int)sizeof(unsigned int)
                         + LSEQ * LSEQ;              // K,V tf32 + mask bytes = 94208
    cudaFuncSetAttribute(attn_mma_kernel,
                         cudaFuncAttributeMaxDynamicSharedMemorySize,
                         smem_bytes);

    attn_mma_kernel<<<nprob, NTHREADS, smem_bytes>>>(q, k, v, mask, out, HN);
}

// round 4
// speedup vs baseline: 4.6116x; 1.5325x over previous
#include <cuda_runtime.h>
#include <cuda_fp16.h>
#include <math.h>

// B=4, H=8, N=128, Lq=Lk=128, D=64. One CTA per (b,h,n); 4 warps; warp owns 32 q rows.
#define LSEQ 128
#define DH   64
#define NTHREADS 128
#define SSTRIDE 72   // halves; 144B row stride -> conflict-free ldmatrix & staging

// Packed mask bits: B*N*L*L / 32 = 262144 words (1 MB) for the fixed shapes.
__device__ unsigned int g_pmask[262144];

__global__ void pack_mask_kernel(const int* __restrict__ mask, int nwords)
{
    const int warp = (blockIdx.x * blockDim.x + threadIdx.x) >> 5;
    const int lane = threadIdx.x & 31;
    if (warp < nwords) {
        const int v = mask[(size_t)warp * 32 + lane];
        const unsigned int bal = __ballot_sync(0xffffffffu, v != 0);
        if (lane == 0) g_pmask[warp] = bal;
    }
}

__device__ __forceinline__ void ldsm_x4(unsigned int* r, const __half* p)
{
    unsigned int a = (unsigned int)__cvta_generic_to_shared(p);
    asm volatile("ldmatrix.sync.aligned.m8n8.x4.shared.b16 {%0,%1,%2,%3}, [%4];"
                 : "=r"(r[0]), "=r"(r[1]), "=r"(r[2]), "=r"(r[3]) : "r"(a));
}

__device__ __forceinline__ void ldsm_x4_trans(unsigned int* r, const __half* p)
{
    unsigned int a = (unsigned int)__cvta_generic_to_shared(p);
    asm volatile("ldmatrix.sync.aligned.m8n8.x4.trans.shared.b16 {%0,%1,%2,%3}, [%4];"
                 : "=r"(r[0]), "=r"(r[1]), "=r"(r[2]), "=r"(r[3]) : "r"(a));
}

__device__ __forceinline__ void mma_f16(float* d, const unsigned int* a,
                                        unsigned int b0, unsigned int b1)
{
    asm volatile(
        "mma.sync.aligned.m16n8k16.row.col.f32.f16.f16.f32 "
        "{%0,%1,%2,%3}, {%4,%5,%6,%7}, {%8,%9}, {%0,%1,%2,%3};"
        : "+f"(d[0]), "+f"(d[1]), "+f"(d[2]), "+f"(d[3])
        : "r"(a[0]), "r"(a[1]), "r"(a[2]), "r"(a[3]), "r"(b0), "r"(b1));
}

__device__ __forceinline__ unsigned int h2u(__half2 h)
{
    union { __half2 h; unsigned int u; } c; c.h = h; return c.u;
}

__global__ __launch_bounds__(NTHREADS, 2)
void attn_mma_fp16(const float* __restrict__ q,
                   const float* __restrict__ k,
                   const float* __restrict__ v,
                   float*       __restrict__ out,
                   int HN)
{
    extern __shared__ __align__(16) char smraw[];
    __half* Qs = (__half*)smraw;
    __half* Ks = Qs + LSEQ * SSTRIDE;
    __half* Vs = Ks + LSEQ * SSTRIDE;

    const int p    = blockIdx.x;
    const int tid  = threadIdx.x;
    const int wid  = tid >> 5;
    const int lane = tid & 31;
    const int g    = lane >> 2;
    const int t    = lane & 3;
    const size_t base = (size_t)p * (LSEQ * DH);

    const int b = p / HN;
    const int n = p % LSEQ;

    // ---- stage Q, K, V as fp16 into smem (coalesced float4 reads) ----
    {
        const float4* qg = (const float4*)(q + base);
        const float4* kg = (const float4*)(k + base);
        const float4* vg = (const float4*)(v + base);
        #pragma unroll
        for (int i = tid; i < LSEQ * (DH / 4); i += NTHREADS) {
            const int row = i >> 4, c4 = i & 15;
            const int off = row * SSTRIDE + c4 * 4;
            float4 a = qg[i];
            *(__half2*)(Qs + off)     = __floats2half2_rn(a.x, a.y);
            *(__half2*)(Qs + off + 2) = __floats2half2_rn(a.z, a.w);
            float4 c = kg[i];
            *(__half2*)(Ks + off)     = __floats2half2_rn(c.x, c.y);
            *(__half2*)(Ks + off + 2) = __floats2half2_rn(c.z, c.w);
            float4 d = vg[i];
            *(__half2*)(Vs + off)     = __floats2half2_rn(d.x, d.y);
            *(__half2*)(Vs + off + 2) = __floats2half2_rn(d.z, d.w);
        }
    }

    // ---- packed mask bits for this thread's 4 rows (mt x h) ----
    uint4 mw[2][2];
    #pragma unroll
    for (int mt = 0; mt < 2; mt++)
        #pragma unroll
        for (int h = 0; h < 2; h++) {
            const int rr = 32 * wid + 16 * mt + g + 8 * h;
            mw[mt][h] = *(const uint4*)(g_pmask +
                         ((size_t)((b * LSEQ + n) * LSEQ + rr)) * 4);
        }

    __syncthreads();

    // ---- Q A-fragments via ldmatrix (rows 32*wid .. +32) ----
    unsigned int qa[2][4][4];
    #pragma unroll
    for (int mt = 0; mt < 2; mt++)
        #pragma unroll
        for (int ks = 0; ks < 4; ks++) {
            const __half* ptr = Qs + (32 * wid + 16 * mt + (lane & 15)) * SSTRIDE
                                   + 16 * ks + ((lane & 16) >> 1);
            ldsm_x4(qa[mt][ks], ptr);
        }

    // ---- online softmax state & O accumulators ----
    float mrow[2][2], lrow[2][2];
    #pragma unroll
    for (int mt = 0; mt < 2; mt++)
        for (int h = 0; h < 2; h++) { mrow[mt][h] = -INFINITY; lrow[mt][h] = 0.0f; }

    float oacc[2][8][4];
    #pragma unroll
    for (int mt = 0; mt < 2; mt++)
        for (int nt = 0; nt < 8; nt++)
            for (int e = 0; e < 4; e++) oacc[mt][nt][e] = 0.0f;

    // ================= main loop over 4 key-blocks of 32 =================
    #pragma unroll 1
    for (int kb = 0; kb < 4; kb++) {
        const int key0 = kb * 32;

        // ---- S = Q @ K^T ----
        float sfr[2][4][4];
        #pragma unroll
        for (int mt = 0; mt < 2; mt++)
            for (int nt = 0; nt < 4; nt++)
                for (int e = 0; e < 4; e++) sfr[mt][nt][e] = 0.0f;

        #pragma unroll
        for (int ntp = 0; ntp < 2; ntp++) {
            #pragma unroll
            for (int ks = 0; ks < 4; ks++) {
                unsigned int kb4[4];
                const __half* kp = Ks + (key0 + 16 * ntp + ((lane & 16) >> 1) + (lane & 7)) * SSTRIDE
                                      + 16 * ks + (lane & 8);
                ldsm_x4(kb4, kp);
                mma_f16(sfr[0][2 * ntp],     qa[0][ks], kb4[0], kb4[1]);
                mma_f16(sfr[0][2 * ntp + 1], qa[0][ks], kb4[2], kb4[3]);
                mma_f16(sfr[1][2 * ntp],     qa[1][ks], kb4[0], kb4[1]);
                mma_f16(sfr[1][2 * ntp + 1], qa[1][ks], kb4[2], kb4[3]);
            }
        }

        // ---- scale + mask + row max ----
        float bm[2][2] = { { -INFINITY, -INFINITY }, { -INFINITY, -INFINITY } };
        #pragma unroll
        for (int mt = 0; mt < 2; mt++) {
            #pragma unroll
            for (int h = 0; h < 2; h++) {
                const uint4 m4 = mw[mt][h];
                const unsigned int w = (kb == 0) ? m4.x : (kb == 1) ? m4.y
                                     : (kb == 2) ? m4.z : m4.w;
                #pragma unroll
                for (int nt = 0; nt < 4; nt++) {
                    const unsigned int sh = (unsigned)(8 * nt + 2 * t);
                    const bool b0 = (w >> sh) & 1u;
                    const bool b1 = (w >> (sh + 1)) & 1u;
                    float e0 = sfr[mt][nt][2 * h];
                    float e1 = sfr[mt][nt][2 * h + 1];
                    e0 = b0 ? e0 * 0.125f : -32768.0f;
                    e1 = b1 ? e1 * 0.125f : -32768.0f;
                    sfr[mt][nt][2 * h]     = e0;
                    sfr[mt][nt][2 * h + 1] = e1;
                    bm[mt][h] = fmaxf(bm[mt][h], fmaxf(e0, e1));
                }
            }
        }
        #pragma unroll
        for (int mt = 0; mt < 2; mt++)
            #pragma unroll
            for (int h = 0; h < 2; h++) {
                float x = bm[mt][h];
                x = fmaxf(x, __shfl_xor_sync(0xffffffff, x, 1));
                x = fmaxf(x, __shfl_xor_sync(0xffffffff, x, 2));
                bm[mt][h] = x;
            }

        // ---- online update ----
        float alpha[2][2];
        float rs[2][2] = { {0.f, 0.f}, {0.f, 0.f} };
        #pragma unroll
        for (int mt = 0; mt < 2; mt++)
            #pragma unroll
            for (int h = 0; h < 2; h++) {
                const float mnew = fmaxf(mrow[mt][h], bm[mt][h]);
                alpha[mt][h] = __expf(mrow[mt][h] - mnew);   // 0 on first block
                mrow[mt][h] = mnew;
            }

        #pragma unroll
        for (int mt = 0; mt < 2; mt++)
            #pragma unroll
            for (int nt = 0; nt < 4; nt++)
                #pragma unroll
                for (int h = 0; h < 2; h++) {
                    float p0 = __expf(sfr[mt][nt][2 * h]     - mrow[mt][h]);
                    float p1 = __expf(sfr[mt][nt][2 * h + 1] - mrow[mt][h]);
                    sfr[mt][nt][2 * h]     = p0;
                    sfr[mt][nt][2 * h + 1] = p1;
                    rs[mt][h] += p0 + p1;
                }

        #pragma unroll
        for (int mt = 0; mt < 2; mt++)
            #pragma unroll
            for (int h = 0; h < 2; h++) {
                float x = rs[mt][h];
                x += __shfl_xor_sync(0xffffffff, x, 1);
                x += __shfl_xor_sync(0xffffffff, x, 2);
                lrow[mt][h] = lrow[mt][h] * alpha[mt][h] + x;
            }

        // rescale O
        #pragma unroll
        for (int mt = 0; mt < 2; mt++)
            #pragma unroll
            for (int nt = 0; nt < 8; nt++) {
                oacc[mt][nt][0] *= alpha[mt][0];
                oacc[mt][nt][1] *= alpha[mt][0];
                oacc[mt][nt][2] *= alpha[mt][1];
                oacc[mt][nt][3] *= alpha[mt][1];
            }

        // ---- P: C-frag pairs ARE the fp16 A-frags (FA2 trick, no shuffles) ----
        unsigned int pa[2][2][4];
        #pragma unroll
        for (int mt = 0; mt < 2; mt++)
            #pragma unroll
            for (int ksp = 0; ksp < 2; ksp++) {
                pa[mt][ksp][0] = h2u(__floats2half2_rn(sfr[mt][2 * ksp][0],     sfr[mt][2 * ksp][1]));
                pa[mt][ksp][1] = h2u(__floats2half2_rn(sfr[mt][2 * ksp][2],     sfr[mt][2 * ksp][3]));
                pa[mt][ksp][2] = h2u(__floats2half2_rn(sfr[mt][2 * ksp + 1][0], sfr[mt][2 * ksp + 1][1]));
                pa[mt][ksp][3] = h2u(__floats2half2_rn(sfr[mt][2 * ksp + 1][2], sfr[mt][2 * ksp + 1][3]));
            }

        // ---- O += P @ V (V fragments via ldmatrix.trans) ----
        #pragma unroll
        for (int ksp = 0; ksp < 2; ksp++) {
            #pragma unroll
            for (int dp = 0; dp < 4; dp++) {
                unsigned int vb4[4];
                const __half* vp = Vs + (key0 + 16 * ksp + (lane & 15)) * SSTRIDE
                                      + 16 * dp + ((lane & 16) >> 1);
                ldsm_x4_trans(vb4, vp);
                mma_f16(oacc[0][2 * dp],     pa[0][ksp], vb4[0], vb4[1]);
                mma_f16(oacc[0][2 * dp + 1], pa[0][ksp], vb4[2], vb4[3]);
                mma_f16(oacc[1][2 * dp],     pa[1][ksp], vb4[0], vb4[1]);
                mma_f16(oacc[1][2 * dp + 1], pa[1][ksp], vb4[2], vb4[3]);
            }
        }
    }

    // ---- epilogue: normalize and store ----
    #pragma unroll
    for (int mt = 0; mt < 2; mt++) {
        const float inv0 = 1.0f / lrow[mt][0];
        const float inv1 = 1.0f / lrow[mt][1];
        const int r0 = 32 * wid + 16 * mt + g;
        #pragma unroll
        for (int nt = 0; nt < 8; nt++) {
            const int col = 8 * nt + 2 * t;
            float2 lo = { oacc[mt][nt][0] * inv0, oacc[mt][nt][1] * inv0 };
            float2 hi = { oacc[mt][nt][2] * inv1, oacc[mt][nt][3] * inv1 };
            *(float2*)(out + base + (size_t)(r0)     * DH + col) = lo;
            *(float2*)(out + base + (size_t)(r0 + 8) * DH + col) = hi;
        }
    }
}

extern "C" void kernel_launch(void* const* d_in, const int* in_sizes, int n_in,
                              void* d_out, int out_size)
{
    const float* q    = (const float*)d_in[0];
    const float* k    = (const float*)d_in[1];
    const float* v    = (const float*)d_in[2];
    const int*   mask = (const int*)d_in[3];
    float*       out  = (float*)d_out;

    const int nprob = in_sizes[0] / (LSEQ * DH);     // B*H*N
    const int nmask = in_sizes[3] / (LSEQ * LSEQ);   // B*N
    const int HN    = (nprob / nmask) * LSEQ;        // H*N

    // pack mask bits (1 word per 32 ints)
    const int nwords = in_sizes[3] / 32;
    pack_mask_kernel<<<(nwords * 32 + 255) / 256, 256>>>(mask, nwords);

    const int smem_bytes = 3 * LSEQ * SSTRIDE * (int)sizeof(__half);  // 55296
    cudaFuncSetAttribute(attn_mma_fp16,
                         cudaFuncAttributeMaxDynamicSharedMemorySize,
                         smem_bytes);

    attn_mma_fp16<<<nprob, NTHREADS, smem_bytes>>>(q, k, v, out, HN);
}

// round 5
// speedup vs baseline: 5.4596x; 1.1839x over previous
#include <cuda_runtime.h>
#include <cuda_fp16.h>
#include <math.h>

// B=4, H=8, N=128, Lq=Lk=128, D=64. One CTA per (b,h,n); 8 warps; warp owns 16 q rows.
#define LSEQ 128
#define DH   64
#define NTHREADS 256
#define SSTRIDE 72   // halves; 144B row stride -> conflict-free ldmatrix & staging

// Packed mask bits: B*N*L*L / 32 = 262144 words (1 MB) for the fixed shapes.
__device__ unsigned int g_pmask[262144];

// Each warp packs 4 consecutive words (128 ints): 4 coalesced LDG.32 + 4 ballots.
__global__ void pack_mask_kernel(const int* __restrict__ mask, int nwords)
{
    const int warp = (blockIdx.x * blockDim.x + threadIdx.x) >> 5;
    const int lane = threadIdx.x & 31;
    const int w0 = warp * 4;
    if (w0 < nwords) {
        #pragma unroll
        for (int w = 0; w < 4; w++) {
            const int v = mask[(size_t)(w0 + w) * 32 + lane];
            const unsigned int bal = __ballot_sync(0xffffffffu, v != 0);
            if (lane == w) g_pmask[w0 + w] = bal;
        }
    }
}

__device__ __forceinline__ void ldsm_x4(unsigned int* r, const __half* p)
{
    unsigned int a = (unsigned int)__cvta_generic_to_shared(p);
    asm volatile("ldmatrix.sync.aligned.m8n8.x4.shared.b16 {%0,%1,%2,%3}, [%4];"
                 : "=r"(r[0]), "=r"(r[1]), "=r"(r[2]), "=r"(r[3]) : "r"(a));
}

__device__ __forceinline__ void ldsm_x4_trans(unsigned int* r, const __half* p)
{
    unsigned int a = (unsigned int)__cvta_generic_to_shared(p);
    asm volatile("ldmatrix.sync.aligned.m8n8.x4.trans.shared.b16 {%0,%1,%2,%3}, [%4];"
                 : "=r"(r[0]), "=r"(r[1]), "=r"(r[2]), "=r"(r[3]) : "r"(a));
}

__device__ __forceinline__ void mma_f16(float* d, const unsigned int* a,
                                        unsigned int b0, unsigned int b1)
{
    asm volatile(
        "mma.sync.aligned.m16n8k16.row.col.f32.f16.f16.f32 "
        "{%0,%1,%2,%3}, {%4,%5,%6,%7}, {%8,%9}, {%0,%1,%2,%3};"
        : "+f"(d[0]), "+f"(d[1]), "+f"(d[2]), "+f"(d[3])
        : "r"(a[0]), "r"(a[1]), "r"(a[2]), "r"(a[3]), "r"(b0), "r"(b1));
}

__device__ __forceinline__ unsigned int h2u(__half2 h)
{
    union { __half2 h; unsigned int u; } c; c.h = h; return c.u;
}

__global__ __launch_bounds__(NTHREADS, 2)
void attn_mma_fp16(const float* __restrict__ q,
                   const float* __restrict__ k,
                   const float* __restrict__ v,
                   float*       __restrict__ out,
                   int HN)
{
    extern __shared__ __align__(16) char smraw[];
    __half* Qs = (__half*)smraw;
    __half* Ks = Qs + LSEQ * SSTRIDE;
    __half* Vs = Ks + LSEQ * SSTRIDE;

    const int p    = blockIdx.x;
    const int tid  = threadIdx.x;
    const int wid  = tid >> 5;          // 0..7, warp owns rows [16*wid, 16*wid+16)
    const int lane = tid & 31;
    const int g    = lane >> 2;
    const int t    = lane & 3;
    const size_t base = (size_t)p * (LSEQ * DH);

    const int b = p / HN;
    const int n = p % LSEQ;

    // ---- stage Q, K, V as fp16 into smem (coalesced float4 reads) ----
    {
        const float4* qg = (const float4*)(q + base);
        const float4* kg = (const float4*)(k + base);
        const float4* vg = (const float4*)(v + base);
        #pragma unroll
        for (int i = tid; i < LSEQ * (DH / 4); i += NTHREADS) {
            const int row = i >> 4, c4 = i & 15;
            const int off = row * SSTRIDE + c4 * 4;
            float4 a = qg[i];
            *(__half2*)(Qs + off)     = __floats2half2_rn(a.x, a.y);
            *(__half2*)(Qs + off + 2) = __floats2half2_rn(a.z, a.w);
            float4 c = kg[i];
            *(__half2*)(Ks + off)     = __floats2half2_rn(c.x, c.y);
            *(__half2*)(Ks + off + 2) = __floats2half2_rn(c.z, c.w);
            float4 d = vg[i];
            *(__half2*)(Vs + off)     = __floats2half2_rn(d.x, d.y);
            *(__half2*)(Vs + off + 2) = __floats2half2_rn(d.z, d.w);
        }
    }

    // ---- packed mask bits for this thread's 2 rows (h=0,1) ----
    uint4 mw[2];
    #pragma unroll
    for (int h = 0; h < 2; h++) {
        const int rr = 16 * wid + g + 8 * h;
        mw[h] = *(const uint4*)(g_pmask +
                 ((size_t)((b * LSEQ + n) * LSEQ + rr)) * 4);
    }

    __syncthreads();

    // ---- Q A-fragments via ldmatrix (rows 16*wid .. +16) ----
    unsigned int qa[4][4];
    #pragma unroll
    for (int ks = 0; ks < 4; ks++) {
        const __half* ptr = Qs + (16 * wid + (lane & 15)) * SSTRIDE
                               + 16 * ks + ((lane & 16) >> 1);
        ldsm_x4(qa[ks], ptr);
    }

    // ---- online softmax state & O accumulators ----
    float mrow[2] = { -INFINITY, -INFINITY };
    float lrow[2] = { 0.0f, 0.0f };

    float oacc[8][4];
    #pragma unroll
    for (int nt = 0; nt < 8; nt++)
        for (int e = 0; e < 4; e++) oacc[nt][e] = 0.0f;

    // ================= main loop over 4 key-blocks of 32 =================
    #pragma unroll 1
    for (int kb = 0; kb < 4; kb++) {
        const int key0 = kb * 32;

        // ---- S = Q @ K^T : sfr[nt] is a 16x8 C-frag (nt over 4 key octets) ----
        float sfr[4][4];
        #pragma unroll
        for (int nt = 0; nt < 4; nt++)
            for (int e = 0; e < 4; e++) sfr[nt][e] = 0.0f;

        #pragma unroll
        for (int ntp = 0; ntp < 2; ntp++) {
            #pragma unroll
            for (int ks = 0; ks < 4; ks++) {
                unsigned int kb4[4];
                const __half* kp = Ks + (key0 + 16 * ntp + ((lane & 16) >> 1) + (lane & 7)) * SSTRIDE
                                      + 16 * ks + (lane & 8);
                ldsm_x4(kb4, kp);
                mma_f16(sfr[2 * ntp],     qa[ks], kb4[0], kb4[1]);
                mma_f16(sfr[2 * ntp + 1], qa[ks], kb4[2], kb4[3]);
            }
        }

        // ---- scale + mask + row max ----
        float bm[2] = { -INFINITY, -INFINITY };
        #pragma unroll
        for (int h = 0; h < 2; h++) {
            const uint4 m4 = mw[h];
            const unsigned int w = (kb == 0) ? m4.x : (kb == 1) ? m4.y
                                 : (kb == 2) ? m4.z : m4.w;
            #pragma unroll
            for (int nt = 0; nt < 4; nt++) {
                const unsigned int sh = (unsigned)(8 * nt + 2 * t);
                const bool b0 = (w >> sh) & 1u;
                const bool b1 = (w >> (sh + 1)) & 1u;
                float e0 = sfr[nt][2 * h];
                float e1 = sfr[nt][2 * h + 1];
                e0 = b0 ? e0 * 0.125f : -32768.0f;
                e1 = b1 ? e1 * 0.125f : -32768.0f;
                sfr[nt][2 * h]     = e0;
                sfr[nt][2 * h + 1] = e1;
                bm[h] = fmaxf(bm[h], fmaxf(e0, e1));
            }
        }
        #pragma unroll
        for (int h = 0; h < 2; h++) {
            float x = bm[h];
            x = fmaxf(x, __shfl_xor_sync(0xffffffff, x, 1));
            x = fmaxf(x, __shfl_xor_sync(0xffffffff, x, 2));
            bm[h] = x;
        }

        // ---- online update ----
        float alpha[2];
        float rs[2] = { 0.f, 0.f };
        #pragma unroll
        for (int h = 0; h < 2; h++) {
            const float mnew = fmaxf(mrow[h], bm[h]);
            alpha[h] = __expf(mrow[h] - mnew);   // 0 on first block
            mrow[h] = mnew;
        }

        #pragma unroll
        for (int nt = 0; nt < 4; nt++)
            #pragma unroll
            for (int h = 0; h < 2; h++) {
                float p0 = __expf(sfr[nt][2 * h]     - mrow[h]);
                float p1 = __expf(sfr[nt][2 * h + 1] - mrow[h]);
                sfr[nt][2 * h]     = p0;
                sfr[nt][2 * h + 1] = p1;
                rs[h] += p0 + p1;
            }

        #pragma unroll
        for (int h = 0; h < 2; h++) {
            float x = rs[h];
            x += __shfl_xor_sync(0xffffffff, x, 1);
            x += __shfl_xor_sync(0xffffffff, x, 2);
            lrow[h] = lrow[h] * alpha[h] + x;
        }

        // rescale O
        #pragma unroll
        for (int nt = 0; nt < 8; nt++) {
            oacc[nt][0] *= alpha[0];
            oacc[nt][1] *= alpha[0];
            oacc[nt][2] *= alpha[1];
            oacc[nt][3] *= alpha[1];
        }

        // ---- P: C-frag pairs ARE the fp16 A-frags (FA2 trick, no shuffles) ----
        unsigned int pa[2][4];
        #pragma unroll
        for (int ksp = 0; ksp < 2; ksp++) {
            pa[ksp][0] = h2u(__floats2half2_rn(sfr[2 * ksp][0],     sfr[2 * ksp][1]));
            pa[ksp][1] = h2u(__floats2half2_rn(sfr[2 * ksp][2],     sfr[2 * ksp][3]));
            pa[ksp][2] = h2u(__floats2half2_rn(sfr[2 * ksp + 1][0], sfr[2 * ksp + 1][1]));
            pa[ksp][3] = h2u(__floats2half2_rn(sfr[2 * ksp + 1][2], sfr[2 * ksp + 1][3]));
        }

        // ---- O += P @ V (V fragments via ldmatrix.trans) ----
        #pragma unroll
        for (int ksp = 0; ksp < 2; ksp++) {
            #pragma unroll
            for (int dp = 0; dp < 4; dp++) {
                unsigned int vb4[4];
                const __half* vp = Vs + (key0 + 16 * ksp + (lane & 15)) * SSTRIDE
                                      + 16 * dp + ((lane & 16) >> 1);
                ldsm_x4_trans(vb4, vp);
                mma_f16(oacc[2 * dp],     pa[ksp], vb4[0], vb4[1]);
                mma_f16(oacc[2 * dp + 1], pa[ksp], vb4[2], vb4[3]);
            }
        }
    }

    // ---- epilogue: normalize and store ----
    {
        const float inv0 = 1.0f / lrow[0];
        const float inv1 = 1.0f / lrow[1];
        const int r0 = 16 * wid + g;
        #pragma unroll
        for (int nt = 0; nt < 8; nt++) {
            const int col = 8 * nt + 2 * t;
            float2 lo = { oacc[nt][0] * inv0, oacc[nt][1] * inv0 };
            float2 hi = { oacc[nt][2] * inv1, oacc[nt][3] * inv1 };
            *(float2*)(out + base + (size_t)(r0)     * DH + col) = lo;
            *(float2*)(out + base + (size_t)(r0 + 8) * DH + col) = hi;
        }
    }
}

extern "C" void kernel_launch(void* const* d_in, const int* in_sizes, int n_in,
                              void* d_out, int out_size)
{
    const float* q    = (const float*)d_in[0];
    const float* k    = (const float*)d_in[1];
    const float* v    = (const float*)d_in[2];
    const int*   mask = (const int*)d_in[3];
    float*       out  = (float*)d_out;

    const int nprob = in_sizes[0] / (LSEQ * DH);     // B*H*N
    const int nmask = in_sizes[3] / (LSEQ * LSEQ);   // B*N
    const int HN    = (nprob / nmask) * LSEQ;        // H*N

    // pack mask bits: each warp packs 4 words
    const int nwords = in_sizes[3] / 32;
    const int nwarps = (nwords + 3) / 4;
    pack_mask_kernel<<<(nwarps * 32 + 255) / 256, 256>>>(mask, nwords);

    const int smem_bytes = 3 * LSEQ * SSTRIDE * (int)sizeof(__half);  // 55296
    cudaFuncSetAttribute(attn_mma_fp16,
                         cudaFuncAttributeMaxDynamicSharedMemorySize,
                         smem_bytes);

    attn_mma_fp16<<<nprob, NTHREADS, smem_bytes>>>(q, k, v, out, HN);
}